// round 7
// baseline (speedup 1.0000x reference)
#include <cuda_runtime.h>
#include <stdint.h>

#define NMAX   100000
#define EMAX   1600000
#define IN_C   128
#define HID_C  128
#define OUT_C  64

#define SCAN_B 256
#define NBLK   ((NMAX + SCAN_B - 1) / SCAN_B)   // 391

// ---------------------------------------------------------------------------
// Scratch (__device__ globals; ~105 MiB, under the alloc guard)
// ---------------------------------------------------------------------------
__device__ float g_xws [(size_t)NMAX * HID_C];   // dinv-scaled X@W (reused L2)
__device__ float g_agg1[(size_t)NMAX * HID_C];   // layer-1 conv output
__device__ float g_dinv[NMAX];
__device__ int   g_deg [NMAX];
__device__ int   g_csr_off[NMAX];
__device__ int   g_cursor [NMAX];
__device__ int   g_csr_src[EMAX];
__device__ int   g_bsum[NBLK + 1];
__device__ int   g_is64;

// ---------------------------------------------------------------------------
// Edge accessor (int64 vs int32 depending on jax x64 config)
// ---------------------------------------------------------------------------
__device__ __forceinline__ int edge_at(const void* ei, int etot, int which, int idx) {
    if (g_is64)
        return (int)((const long long*)ei)[(size_t)which * etot + idx];
    else
        return ((const int*)ei)[(size_t)which * etot + idx];
}

__global__ void k_detect(const int* ei32) {
    int ok64 = 1;
#pragma unroll
    for (int i = 0; i < 16; i++)
        if (ei32[2 * i + 1] != 0) ok64 = 0;
    g_is64 = ok64;
}

// ---------------------------------------------------------------------------
// Degree / normalization
// ---------------------------------------------------------------------------
__global__ void k_deg_zero(int n) {
    int i = blockIdx.x * blockDim.x + threadIdx.x;
    if (i < n) g_deg[i] = 0;
}

__global__ void k_deg_count(const void* ei, int e) {
    int i = blockIdx.x * blockDim.x + threadIdx.x;
    if (i < e) atomicAdd(&g_deg[edge_at(ei, e, 1, i)], 1);
}

__global__ void k_dinv(int n) {
    int i = blockIdx.x * blockDim.x + threadIdx.x;
    if (i < n) g_dinv[i] = rsqrtf((float)(g_deg[i] + 1));
}

// ---------------------------------------------------------------------------
// 3-phase parallel exclusive scan
// ---------------------------------------------------------------------------
__global__ void __launch_bounds__(SCAN_B) k_scanA(int n) {
    __shared__ int sh[SCAN_B / 32];
    int i = blockIdx.x * SCAN_B + threadIdx.x;
    int v = (i < n) ? g_deg[i] : 0;
#pragma unroll
    for (int o = 16; o > 0; o >>= 1) v += __shfl_down_sync(0xffffffffu, v, o);
    if ((threadIdx.x & 31) == 0) sh[threadIdx.x >> 5] = v;
    __syncthreads();
    if (threadIdx.x < SCAN_B / 32) {
        int w = sh[threadIdx.x];
#pragma unroll
        for (int o = SCAN_B / 64; o > 0; o >>= 1)
            w += __shfl_down_sync(0xffffffffu, w, o, SCAN_B / 32);
        if (threadIdx.x == 0) g_bsum[blockIdx.x] = w;
    }
}

__global__ void __launch_bounds__(512) k_scanB(int nblk) {
    __shared__ int sh[512];
    int tid = threadIdx.x;
    int v = (tid < nblk) ? g_bsum[tid] : 0;
    sh[tid] = v;
    __syncthreads();
    for (int d = 1; d < 512; d <<= 1) {
        int t = (tid >= d) ? sh[tid - d] : 0;
        __syncthreads();
        sh[tid] += t;
        __syncthreads();
    }
    if (tid < nblk) g_bsum[tid] = sh[tid] - v;
}

__global__ void __launch_bounds__(SCAN_B) k_scanC(int n) {
    __shared__ int sh[SCAN_B];
    int i   = blockIdx.x * SCAN_B + threadIdx.x;
    int tid = threadIdx.x;
    int v = (i < n) ? g_deg[i] : 0;
    sh[tid] = v;
    __syncthreads();
    for (int d = 1; d < SCAN_B; d <<= 1) {
        int t = (tid >= d) ? sh[tid - d] : 0;
        __syncthreads();
        sh[tid] += t;
        __syncthreads();
    }
    if (i < n) {
        int off = g_bsum[blockIdx.x] + sh[tid] - v;
        g_csr_off[i] = off;
        g_cursor[i]  = off;
    }
}

__global__ void k_csr_build(const void* ei, int e) {
    int i = blockIdx.x * blockDim.x + threadIdx.x;
    if (i < e) {
        int s = edge_at(ei, e, 0, i);
        int d = edge_at(ei, e, 1, i);
        int slot = atomicAdd(&g_cursor[d], 1);
        g_csr_src[slot] = s;
    }
}

// ---------------------------------------------------------------------------
// TF32 helpers
// ---------------------------------------------------------------------------
__device__ __forceinline__ uint32_t f2tf32(float f) {
    uint32_t r;
    asm("cvt.rna.tf32.f32 %0, %1;" : "=r"(r) : "f"(f));
    return r;
}

__device__ __forceinline__ void mma_tf32(float* d, const uint32_t* a,
                                         const uint32_t* b) {
    asm volatile(
        "mma.sync.aligned.m16n8k8.row.col.f32.tf32.tf32.f32 "
        "{%0,%1,%2,%3}, {%4,%5,%6,%7}, {%8,%9}, {%0,%1,%2,%3};\n"
        : "+f"(d[0]), "+f"(d[1]), "+f"(d[2]), "+f"(d[3])
        : "r"(a[0]), "r"(a[1]), "r"(a[2]), "r"(a[3]), "r"(b[0]), "r"(b[1]));
}

// ---------------------------------------------------------------------------
// Tensor-core GEMM (3xTF32, ~fp32 accuracy):
//   L==1 : A = X (input x)           -> g_xws = dinv * (x @ W1)
//   L==2 : A = relu(g_agg1 + b1)     -> g_xws = dinv * (h @ W2)
// Block = 256 thr (8 warps), 128-row tile. Warp w: rows 16w..16w+15, all COUT.
// smem: A[128][132] fp32 ; Wt_big[COUT][132] ; Wt_res[COUT][132]
// ---------------------------------------------------------------------------
template <int CIN, int COUT, int L>
__global__ void __launch_bounds__(256, 1)
k_gemm_mma(const float* __restrict__ X, const float* __restrict__ W,
           const float* __restrict__ bin, int n)
{
    constexpr int PAD = 132;
    constexpr int NT  = COUT / 8;                 // n-tiles per warp
    extern __shared__ float sm[];
    float* As = sm;                               // 128 * PAD
    float* Bb = As + 128 * PAD;                   // COUT * PAD
    float* Br = Bb + COUT * PAD;                  // COUT * PAD

    const int tid  = threadIdx.x;
    const int row0 = blockIdx.x * 128;

    // W -> transposed big/res split in smem (W is [CIN][COUT] row-major)
    for (int idx = tid; idx < CIN * COUT; idx += 256) {
        int k  = idx / COUT;
        int nn = idx - k * COUT;
        float w = W[idx];
        uint32_t big = f2tf32(w);
        float res = w - __uint_as_float(big);
        Bb[nn * PAD + k] = __uint_as_float(big);
        Br[nn * PAD + k] = __uint_as_float(f2tf32(res));
    }

    // A tile (zero-fill rows beyond n). L==1 reads X; L==2 reads g_agg1 with
    // fused +b1, relu.
    const float* __restrict__ src = (L == 1) ? X : g_agg1;
    for (int idx = tid; idx < 128 * (CIN / 4); idx += 256) {
        int r  = idx / (CIN / 4);
        int c4 = (idx - r * (CIN / 4)) * 4;
        float4 v = make_float4(0.f, 0.f, 0.f, 0.f);
        if (row0 + r < n) {
            v = *(const float4*)(src + (size_t)(row0 + r) * CIN + c4);
            if (L == 2) {
                float4 b = *(const float4*)(bin + c4);
                v.x = fmaxf(v.x + b.x, 0.f);
                v.y = fmaxf(v.y + b.y, 0.f);
                v.z = fmaxf(v.z + b.z, 0.f);
                v.w = fmaxf(v.w + b.w, 0.f);
            }
        }
        *(float4*)(As + r * PAD + c4) = v;
    }
    __syncthreads();

    const int w    = tid >> 5;
    const int lane = tid & 31;
    const int g    = lane >> 2;                   // group id (0..7)
    const int t    = lane & 3;                    // thread-in-group (0..3)
    const int arow = w * 16;

    float acc[NT][4];
#pragma unroll
    for (int i = 0; i < NT; i++) {
        acc[i][0] = acc[i][1] = acc[i][2] = acc[i][3] = 0.f;
    }

    for (int k0 = 0; k0 < CIN; k0 += 8) {
        // A fragment (m16n8k8 row-major layout)
        float a0 = As[(arow + g)     * PAD + k0 + t];
        float a1 = As[(arow + g + 8) * PAD + k0 + t];
        float a2 = As[(arow + g)     * PAD + k0 + t + 4];
        float a3 = As[(arow + g + 8) * PAD + k0 + t + 4];
        uint32_t ab[4] = { f2tf32(a0), f2tf32(a1), f2tf32(a2), f2tf32(a3) };
        uint32_t ar[4] = { f2tf32(a0 - __uint_as_float(ab[0])),
                           f2tf32(a1 - __uint_as_float(ab[1])),
                           f2tf32(a2 - __uint_as_float(ab[2])),
                           f2tf32(a3 - __uint_as_float(ab[3])) };
#pragma unroll
        for (int nt = 0; nt < NT; nt++) {
            int nb = nt * 8 + g;                  // B col-major: col=g, row=k
            uint32_t bb[2], br2[2];
            bb[0]  = __float_as_uint(Bb[nb * PAD + k0 + t]);
            bb[1]  = __float_as_uint(Bb[nb * PAD + k0 + t + 4]);
            br2[0] = __float_as_uint(Br[nb * PAD + k0 + t]);
            br2[1] = __float_as_uint(Br[nb * PAD + k0 + t + 4]);
            mma_tf32(acc[nt], ab, bb);            // big*big
            mma_tf32(acc[nt], ab, br2);           // big*res
            mma_tf32(acc[nt], ar, bb);            // res*big
        }
    }

    // Epilogue: dinv-prescale, write g_xws. C layout: c0(g,2t) c1(g,2t+1)
    // c2(g+8,2t) c3(g+8,2t+1).
    int r0 = row0 + arow + g;
    int r1 = r0 + 8;
    float d0 = (r0 < n) ? g_dinv[r0] : 0.f;
    float d1 = (r1 < n) ? g_dinv[r1] : 0.f;
#pragma unroll
    for (int nt = 0; nt < NT; nt++) {
        int col = nt * 8 + t * 2;
        if (r0 < n) {
            float2 v = make_float2(d0 * acc[nt][0], d0 * acc[nt][1]);
            *(float2*)(g_xws + (size_t)r0 * COUT + col) = v;
        }
        if (r1 < n) {
            float2 v = make_float2(d1 * acc[nt][2], d1 * acc[nt][3]);
            *(float2*)(g_xws + (size_t)r1 * COUT + col) = v;
        }
    }
}

// ---------------------------------------------------------------------------
// Pull aggregation (vectorized): C/4 lanes per node, float4 per lane.
// ---------------------------------------------------------------------------
template <int C, int L>
__global__ void k_agg(float* __restrict__ extout, const float* __restrict__ b2,
                      int n)
{
    constexpr int LANES = C / 4;
    int node = blockIdx.x * blockDim.y + threadIdx.y;
    if (node >= n) return;
    int lane = threadIdx.x;

    const float4* __restrict__ xw = (const float4*)g_xws;

    int beg = g_csr_off[node];
    int end = beg + g_deg[node];

    float4 a = xw[(size_t)node * LANES + lane];     // self-loop term
    float ax = a.x, ay = a.y, az = a.z, aw = a.w;

    int j = beg;
    for (; j + 4 <= end; j += 4) {
        int s0 = g_csr_src[j + 0];
        int s1 = g_csr_src[j + 1];
        int s2 = g_csr_src[j + 2];
        int s3 = g_csr_src[j + 3];
        float4 v0 = xw[(size_t)s0 * LANES + lane];
        float4 v1 = xw[(size_t)s1 * LANES + lane];
        float4 v2 = xw[(size_t)s2 * LANES + lane];
        float4 v3 = xw[(size_t)s3 * LANES + lane];
        ax += v0.x + v1.x + v2.x + v3.x;
        ay += v0.y + v1.y + v2.y + v3.y;
        az += v0.z + v1.z + v2.z + v3.z;
        aw += v0.w + v1.w + v2.w + v3.w;
    }
    for (; j < end; ++j) {
        float4 v = xw[(size_t)g_csr_src[j] * LANES + lane];
        ax += v.x; ay += v.y; az += v.z; aw += v.w;
    }

    float di = g_dinv[node];
    float4 r;
    r.x = di * ax; r.y = di * ay; r.z = di * az; r.w = di * aw;

    if (L == 1) {
        ((float4*)g_agg1)[(size_t)node * LANES + lane] = r;
    } else {
        const float4 bb = ((const float4*)b2)[lane];
        r.x += bb.x; r.y += bb.y; r.z += bb.z; r.w += bb.w;
        ((float4*)extout)[(size_t)node * LANES + lane] = r;
    }
}

// ---------------------------------------------------------------------------
// Launch
// ---------------------------------------------------------------------------
extern "C" void kernel_launch(void* const* d_in, const int* in_sizes, int n_in,
                              void* d_out, int out_size)
{
    const float* x  = (const float*)d_in[0];
    const void*  ei = d_in[1];
    const float* W1 = (const float*)d_in[2];
    const float* b1 = (const float*)d_in[3];
    const float* W2 = (const float*)d_in[4];
    const float* b2 = (const float*)d_in[5];
    float*       out = (float*)d_out;

    const int n = in_sizes[0] / IN_C;     // 100000
    const int e = in_sizes[1] / 2;        // 1600000
    const int TB = 256;
    const int nblk = (n + SCAN_B - 1) / SCAN_B;

    // Dynamic smem: A(128) + Wt_big(COUT) + Wt_res(COUT), rows padded to 132.
    const int smem1 = (128 + 2 * HID_C) * 132 * 4;   // 202752 B
    const int smem2 = (128 + 2 * OUT_C) * 132 * 4;   // 135168 B
    cudaFuncSetAttribute(k_gemm_mma<IN_C, HID_C, 1>,
                         cudaFuncAttributeMaxDynamicSharedMemorySize, smem1);
    cudaFuncSetAttribute(k_gemm_mma<HID_C, OUT_C, 2>,
                         cudaFuncAttributeMaxDynamicSharedMemorySize, smem2);

    k_detect   <<<1, 1>>>((const int*)ei);
    k_deg_zero <<<(n + TB - 1) / TB, TB>>>(n);
    k_deg_count<<<(e + TB - 1) / TB, TB>>>(ei, e);
    k_scanA    <<<nblk, SCAN_B>>>(n);
    k_scanB    <<<1, 512>>>(nblk);
    k_scanC    <<<nblk, SCAN_B>>>(n);
    k_dinv     <<<(n + TB - 1) / TB, TB>>>(n);
    k_csr_build<<<(e + TB - 1) / TB, TB>>>(ei, e);

    const int gblk = (n + 127) / 128;

    // Layer 1
    k_gemm_mma<IN_C, HID_C, 1><<<gblk, 256, smem1>>>(x, W1, nullptr, n);
    {
        dim3 blk(HID_C / 4, 8);
        k_agg<HID_C, 1><<<(n + 7) / 8, blk>>>(nullptr, nullptr, n);
    }

    // Layer 2
    k_gemm_mma<HID_C, OUT_C, 2><<<gblk, 256, smem2>>>(nullptr, W2, b1, n);
    {
        dim3 blk(OUT_C / 4, 16);
        k_agg<OUT_C, 2><<<(n + 15) / 16, blk>>>(out, b2, n);
    }
}

// round 9
// speedup vs baseline: 1.3143x; 1.3143x over previous
#include <cuda_runtime.h>
#include <stdint.h>

#define NMAX   100000
#define EMAX   1600000
#define IN_C   128
#define HID_C  128
#define OUT_C  64

#define SCAN_B 256
#define NBLK   ((NMAX + SCAN_B - 1) / SCAN_B)   // 391

// ---------------------------------------------------------------------------
// Scratch (__device__ globals; ~106 MiB, under the alloc guard)
// ---------------------------------------------------------------------------
__device__ float g_xws [(size_t)NMAX * HID_C];   // dinv-scaled X@W (reused L2)
__device__ float g_agg1[(size_t)NMAX * HID_C];   // layer-1 conv output
__device__ float g_dinv[NMAX];
__device__ int   g_deg [NMAX];
__device__ int   g_csr_off[NMAX];
__device__ int   g_cursor [NMAX];
__device__ int   g_csr_src[EMAX];
__device__ int   g_bsum[NBLK + 1];
__device__ int   g_is64;
// Fragment-ordered W (big/res tf32 split), built once per launch:
//   layout [ks][nb][t] -> float4 {big(k0+t,nb), big(k0+t+4,nb),
//                                 res(k0+t,nb), res(k0+t+4,nb)},  k0 = ks*8
__device__ float4 g_wf1[(IN_C / 8) * HID_C * 4];   // 8192 float4 = 128 KB
__device__ float4 g_wf2[(HID_C / 8) * OUT_C * 4];  // 4096 float4 =  64 KB

// ---------------------------------------------------------------------------
// Edge accessor (int64 vs int32 depending on jax x64 config)
// ---------------------------------------------------------------------------
__device__ __forceinline__ int edge_at(const void* ei, int etot, int which, int idx) {
    if (g_is64)
        return (int)((const long long*)ei)[(size_t)which * etot + idx];
    else
        return ((const int*)ei)[(size_t)which * etot + idx];
}

__global__ void k_detect(const int* ei32) {
    int ok64 = 1;
#pragma unroll
    for (int i = 0; i < 16; i++)
        if (ei32[2 * i + 1] != 0) ok64 = 0;
    g_is64 = ok64;
}

// ---------------------------------------------------------------------------
// Degree / normalization
// ---------------------------------------------------------------------------
__global__ void k_deg_zero(int n) {
    int i = blockIdx.x * blockDim.x + threadIdx.x;
    if (i < n) g_deg[i] = 0;
}

__global__ void k_deg_count(const void* ei, int e) {
    int i = blockIdx.x * blockDim.x + threadIdx.x;
    if (i < e) atomicAdd(&g_deg[edge_at(ei, e, 1, i)], 1);
}

__global__ void k_dinv(int n) {
    int i = blockIdx.x * blockDim.x + threadIdx.x;
    if (i < n) g_dinv[i] = rsqrtf((float)(g_deg[i] + 1));
}

// ---------------------------------------------------------------------------
// 3-phase parallel exclusive scan
// ---------------------------------------------------------------------------
__global__ void __launch_bounds__(SCAN_B) k_scanA(int n) {
    __shared__ int sh[SCAN_B / 32];
    int i = blockIdx.x * SCAN_B + threadIdx.x;
    int v = (i < n) ? g_deg[i] : 0;
#pragma unroll
    for (int o = 16; o > 0; o >>= 1) v += __shfl_down_sync(0xffffffffu, v, o);
    if ((threadIdx.x & 31) == 0) sh[threadIdx.x >> 5] = v;
    __syncthreads();
    if (threadIdx.x < SCAN_B / 32) {
        int w = sh[threadIdx.x];
#pragma unroll
        for (int o = SCAN_B / 64; o > 0; o >>= 1)
            w += __shfl_down_sync(0xffffffffu, w, o, SCAN_B / 32);
        if (threadIdx.x == 0) g_bsum[blockIdx.x] = w;
    }
}

__global__ void __launch_bounds__(512) k_scanB(int nblk) {
    __shared__ int sh[512];
    int tid = threadIdx.x;
    int v = (tid < nblk) ? g_bsum[tid] : 0;
    sh[tid] = v;
    __syncthreads();
    for (int d = 1; d < 512; d <<= 1) {
        int t = (tid >= d) ? sh[tid - d] : 0;
        __syncthreads();
        sh[tid] += t;
        __syncthreads();
    }
    if (tid < nblk) g_bsum[tid] = sh[tid] - v;
}

__global__ void __launch_bounds__(SCAN_B) k_scanC(int n) {
    __shared__ int sh[SCAN_B];
    int i   = blockIdx.x * SCAN_B + threadIdx.x;
    int tid = threadIdx.x;
    int v = (i < n) ? g_deg[i] : 0;
    sh[tid] = v;
    __syncthreads();
    for (int d = 1; d < SCAN_B; d <<= 1) {
        int t = (tid >= d) ? sh[tid - d] : 0;
        __syncthreads();
        sh[tid] += t;
        __syncthreads();
    }
    if (i < n) {
        int off = g_bsum[blockIdx.x] + sh[tid] - v;
        g_csr_off[i] = off;
        g_cursor[i]  = off;
    }
}

__global__ void k_csr_build(const void* ei, int e) {
    int i = blockIdx.x * blockDim.x + threadIdx.x;
    if (i < e) {
        int s = edge_at(ei, e, 0, i);
        int d = edge_at(ei, e, 1, i);
        int slot = atomicAdd(&g_cursor[d], 1);
        g_csr_src[slot] = s;
    }
}

// ---------------------------------------------------------------------------
// TF32 helpers
// ---------------------------------------------------------------------------
__device__ __forceinline__ uint32_t f2tf32(float f) {
    uint32_t r;
    asm("cvt.rna.tf32.f32 %0, %1;" : "=r"(r) : "f"(f));
    return r;
}

__device__ __forceinline__ void mma_tf32(float* d, const uint32_t* a,
                                         const uint32_t* b) {
    asm volatile(
        "mma.sync.aligned.m16n8k8.row.col.f32.tf32.tf32.f32 "
        "{%0,%1,%2,%3}, {%4,%5,%6,%7}, {%8,%9}, {%0,%1,%2,%3};\n"
        : "+f"(d[0]), "+f"(d[1]), "+f"(d[2]), "+f"(d[3])
        : "r"(a[0]), "r"(a[1]), "r"(a[2]), "r"(a[3]), "r"(b[0]), "r"(b[1]));
}

// ---------------------------------------------------------------------------
// One-time W split into fragment-ordered big/res tf32 (global, L2-resident).
// idx -> t = idx&3, nb = (idx>>2)%COUT, ks = idx/(4*COUT); k0 = ks*8.
// ---------------------------------------------------------------------------
template <int CIN, int COUT>
__global__ void k_wsplit(const float* __restrict__ W, float4* __restrict__ wf)
{
    int idx = blockIdx.x * blockDim.x + threadIdx.x;
    int total = (CIN / 8) * COUT * 4;
    if (idx >= total) return;
    int t  = idx & 3;
    int nb = (idx >> 2) % COUT;
    int ks = idx / (4 * COUT);
    int k0 = ks * 8;
    float w0 = W[(k0 + t)     * COUT + nb];
    float w1 = W[(k0 + t + 4) * COUT + nb];
    uint32_t b0 = f2tf32(w0), b1 = f2tf32(w1);
    float4 v;
    v.x = __uint_as_float(b0);
    v.y = __uint_as_float(b1);
    v.z = __uint_as_float(f2tf32(w0 - __uint_as_float(b0)));
    v.w = __uint_as_float(f2tf32(w1 - __uint_as_float(b1)));
    wf[idx] = v;
}

// ---------------------------------------------------------------------------
// Tensor-core GEMM (3xTF32): dynamic smem holds ONLY the A tile (67.5 KB)
// -> 3 CTAs/SM.  B fragments stream from fragment-ordered W in L2
// (1 coalesced LDG.128 per n-tile per k-step).  Block = 256 thr (8 warps),
// 128-row tile; warp w owns rows 16w..16w+15 and all COUT columns.
//   L==1 : A = X            -> g_xws = dinv * (x @ W1)
//   L==2 : A = relu(agg1+b1)-> g_xws = dinv * (h @ W2)
// ---------------------------------------------------------------------------
template <int CIN, int COUT, int L>
__global__ void __launch_bounds__(256)
k_gemm_mma(const float* __restrict__ X, const float4* __restrict__ wf,
           const float* __restrict__ bin, int n)
{
    constexpr int PAD = 132;
    constexpr int NT  = COUT / 8;
    extern __shared__ float As[];                 // 128 * PAD floats (dynamic)

    const int tid  = threadIdx.x;
    const int row0 = blockIdx.x * 128;

    // A tile (zero-fill rows beyond n). L==2 fuses +b1, relu.
    const float* __restrict__ src = (L == 1) ? X : g_agg1;
    for (int idx = tid; idx < 128 * (CIN / 4); idx += 256) {
        int r  = idx / (CIN / 4);
        int c4 = (idx - r * (CIN / 4)) * 4;
        float4 v = make_float4(0.f, 0.f, 0.f, 0.f);
        if (row0 + r < n) {
            v = *(const float4*)(src + (size_t)(row0 + r) * CIN + c4);
            if (L == 2) {
                float4 b = *(const float4*)(bin + c4);
                v.x = fmaxf(v.x + b.x, 0.f);
                v.y = fmaxf(v.y + b.y, 0.f);
                v.z = fmaxf(v.z + b.z, 0.f);
                v.w = fmaxf(v.w + b.w, 0.f);
            }
        }
        *(float4*)(As + r * PAD + c4) = v;
    }
    __syncthreads();

    const int w    = tid >> 5;
    const int lane = tid & 31;
    const int g    = lane >> 2;                   // 0..7
    const int t    = lane & 3;                    // 0..3
    const int arow = w * 16;

    float acc[NT][4];
#pragma unroll
    for (int i = 0; i < NT; i++) {
        acc[i][0] = acc[i][1] = acc[i][2] = acc[i][3] = 0.f;
    }

#pragma unroll 2
    for (int ks = 0; ks < CIN / 8; ks++) {
        const int k0 = ks * 8;
        // A fragment (m16n8k8 row-major)
        float a0 = As[(arow + g)     * PAD + k0 + t];
        float a1 = As[(arow + g + 8) * PAD + k0 + t];
        float a2 = As[(arow + g)     * PAD + k0 + t + 4];
        float a3 = As[(arow + g + 8) * PAD + k0 + t + 4];
        uint32_t ab[4] = { f2tf32(a0), f2tf32(a1), f2tf32(a2), f2tf32(a3) };
        uint32_t ar[4] = { f2tf32(a0 - __uint_as_float(ab[0])),
                           f2tf32(a1 - __uint_as_float(ab[1])),
                           f2tf32(a2 - __uint_as_float(ab[2])),
                           f2tf32(a3 - __uint_as_float(ab[3])) };
        const float4* wrow = wf + (size_t)ks * (COUT * 4);
#pragma unroll
        for (int nt = 0; nt < NT; nt++) {
            int nb = nt * 8 + g;
            float4 f = __ldg(&wrow[nb * 4 + t]);  // coalesced 16B/lane, L2-hot
            uint32_t bb[2]  = { __float_as_uint(f.x), __float_as_uint(f.y) };
            uint32_t br2[2] = { __float_as_uint(f.z), __float_as_uint(f.w) };
            mma_tf32(acc[nt], ab, bb);            // big*big
            mma_tf32(acc[nt], ab, br2);           // big*res
            mma_tf32(acc[nt], ar, bb);            // res*big
        }
    }

    // Epilogue: dinv-prescale, write g_xws. C cols: 2t, 2t+1; rows g, g+8.
    int r0 = row0 + arow + g;
    int r1 = r0 + 8;
    float d0 = (r0 < n) ? g_dinv[r0] : 0.f;
    float d1 = (r1 < n) ? g_dinv[r1] : 0.f;
#pragma unroll
    for (int nt = 0; nt < NT; nt++) {
        int col = nt * 8 + t * 2;
        if (r0 < n) {
            float2 v = make_float2(d0 * acc[nt][0], d0 * acc[nt][1]);
            *(float2*)(g_xws + (size_t)r0 * COUT + col) = v;
        }
        if (r1 < n) {
            float2 v = make_float2(d1 * acc[nt][2], d1 * acc[nt][3]);
            *(float2*)(g_xws + (size_t)r1 * COUT + col) = v;
        }
    }
}

// ---------------------------------------------------------------------------
// Pull aggregation (vectorized): C/4 lanes per node, float4 per lane.
// ---------------------------------------------------------------------------
template <int C, int L>
__global__ void k_agg(float* __restrict__ extout, const float* __restrict__ b2,
                      int n)
{
    constexpr int LANES = C / 4;
    int node = blockIdx.x * blockDim.y + threadIdx.y;
    if (node >= n) return;
    int lane = threadIdx.x;

    const float4* __restrict__ xw = (const float4*)g_xws;

    int beg = g_csr_off[node];
    int end = beg + g_deg[node];

    float4 a = xw[(size_t)node * LANES + lane];     // self-loop term
    float ax = a.x, ay = a.y, az = a.z, aw = a.w;

    int j = beg;
    for (; j + 4 <= end; j += 4) {
        int s0 = g_csr_src[j + 0];
        int s1 = g_csr_src[j + 1];
        int s2 = g_csr_src[j + 2];
        int s3 = g_csr_src[j + 3];
        float4 v0 = xw[(size_t)s0 * LANES + lane];
        float4 v1 = xw[(size_t)s1 * LANES + lane];
        float4 v2 = xw[(size_t)s2 * LANES + lane];
        float4 v3 = xw[(size_t)s3 * LANES + lane];
        ax += v0.x + v1.x + v2.x + v3.x;
        ay += v0.y + v1.y + v2.y + v3.y;
        az += v0.z + v1.z + v2.z + v3.z;
        aw += v0.w + v1.w + v2.w + v3.w;
    }
    for (; j < end; ++j) {
        float4 v = xw[(size_t)g_csr_src[j] * LANES + lane];
        ax += v.x; ay += v.y; az += v.z; aw += v.w;
    }

    float di = g_dinv[node];
    float4 r;
    r.x = di * ax; r.y = di * ay; r.z = di * az; r.w = di * aw;

    if (L == 1) {
        ((float4*)g_agg1)[(size_t)node * LANES + lane] = r;
    } else {
        const float4 bb = ((const float4*)b2)[lane];
        r.x += bb.x; r.y += bb.y; r.z += bb.z; r.w += bb.w;
        ((float4*)extout)[(size_t)node * LANES + lane] = r;
    }
}

// ---------------------------------------------------------------------------
// Launch
// ---------------------------------------------------------------------------
extern "C" void kernel_launch(void* const* d_in, const int* in_sizes, int n_in,
                              void* d_out, int out_size)
{
    const float* x  = (const float*)d_in[0];
    const void*  ei = d_in[1];
    const float* W1 = (const float*)d_in[2];
    const float* b1 = (const float*)d_in[3];
    const float* W2 = (const float*)d_in[4];
    const float* b2 = (const float*)d_in[5];
    float*       out = (float*)d_out;

    const int n = in_sizes[0] / IN_C;     // 100000
    const int e = in_sizes[1] / 2;        // 1600000
    const int TB = 256;
    const int nblk = (n + SCAN_B - 1) / SCAN_B;

    // Dynamic smem for the A tile: 128 rows x 132 floats = 67584 B (>48KB
    // static cap -> must be dynamic + opt-in attribute).
    const int smemA = 128 * 132 * 4;
    cudaFuncSetAttribute(k_gemm_mma<IN_C, HID_C, 1>,
                         cudaFuncAttributeMaxDynamicSharedMemorySize, smemA);
    cudaFuncSetAttribute(k_gemm_mma<HID_C, OUT_C, 2>,
                         cudaFuncAttributeMaxDynamicSharedMemorySize, smemA);

    k_detect   <<<1, 1>>>((const int*)ei);
    k_deg_zero <<<(n + TB - 1) / TB, TB>>>(n);
    k_deg_count<<<(e + TB - 1) / TB, TB>>>(ei, e);
    k_scanA    <<<nblk, SCAN_B>>>(n);
    k_scanB    <<<1, 512>>>(nblk);
    k_scanC    <<<nblk, SCAN_B>>>(n);
    k_dinv     <<<(n + TB - 1) / TB, TB>>>(n);
    k_csr_build<<<(e + TB - 1) / TB, TB>>>(ei, e);

    // One-time W fragment splits (tiny)
    float4* wf1;  cudaGetSymbolAddress((void**)&wf1, g_wf1);
    float4* wf2;  cudaGetSymbolAddress((void**)&wf2, g_wf2);
    {
        const int t1 = (IN_C / 8) * HID_C * 4;    // 8192
        const int t2 = (HID_C / 8) * OUT_C * 4;   // 4096
        k_wsplit<IN_C, HID_C><<<(t1 + 255) / 256, 256>>>(W1, wf1);
        k_wsplit<HID_C, OUT_C><<<(t2 + 255) / 256, 256>>>(W2, wf2);
    }

    const int gblk = (n + 127) / 128;

    // Layer 1
    k_gemm_mma<IN_C, HID_C, 1><<<gblk, 256, smemA>>>(x, wf1, nullptr, n);
    {
        dim3 blk(HID_C / 4, 8);
        k_agg<HID_C, 1><<<(n + 7) / 8, blk>>>(nullptr, nullptr, n);
    }

    // Layer 2
    k_gemm_mma<HID_C, OUT_C, 2><<<gblk, 256, smemA>>>(nullptr, wf2, b1, n);
    {
        dim3 blk(OUT_C / 4, 16);
        k_agg<OUT_C, 2><<<(n + 15) / 16, blk>>>(out, b2, n);
    }
}